// round 15
// baseline (speedup 1.0000x reference)
#include <cuda_runtime.h>
#include <cuda_fp16.h>
#include <cuda_bf16.h>

// Problem constants
#define NB     50      // buckets
#define HID    32
#define HALF   16
#define GRID   608     // 152 SMs * 4 resident blocks (persistent grid-stride)
#define BLOCK  256

typedef unsigned long long ull;

// Precomputed tables (device globals — no allocation allowed).
// g_vh: per bucket id, 9 uint2 slots (stride 9; slots 0..7 hold v[id][4q..4q+3]
// as 4 halves, slot 8 = pad). Bank-pair group of slot q is (9*id+q) mod 16 ->
// good spread for random ids, linear addressing (imm offsets).
__device__ uint2  g_vh[NB * 9];
__device__ float  g_c[NB];       // c[id] = b2 . Wh[id] + bh[id]  (fp32)
// W1/b1 interleaved for broadcast LDS.128:
//   g_W[3q+0] = {A[4q..4q+3]}  (A = W1[0][:])
//   g_W[3q+1] = {B[4q..4q+3]}  (B = W1[1][:])
//   g_W[3q+2] = {C[4q..4q+3]}  (C = b1[:])
__device__ float4 g_W[3 * HID / 4];

// ---------------------------------------------------------------------------
// Packed f32x2 helpers (Blackwell FFMA2 — only reachable via explicit PTX).
// ---------------------------------------------------------------------------
__device__ __forceinline__ ull pack2(float lo, float hi) {
    ull r;
    asm("mov.b64 %0, {%1, %2};" : "=l"(r) : "f"(lo), "f"(hi));
    return r;
}
__device__ __forceinline__ ull fma2(ull a, ull b, ull c) {
    ull d;
    asm("fma.rn.f32x2 %0, %1, %2, %3;" : "=l"(d) : "l"(a), "l"(b), "l"(c));
    return d;
}
__device__ __forceinline__ ull relu2(ull t) {
    float lo, hi;
    asm("mov.b64 {%0, %1}, %2;" : "=f"(lo), "=f"(hi) : "l"(t));
    return pack2(fmaxf(lo, 0.f), fmaxf(hi, 0.f));
}
__device__ __forceinline__ float hsum2(ull t) {
    float lo, hi;
    asm("mov.b64 {%0, %1}, %2;" : "=f"(lo), "=f"(hi) : "l"(t));
    return lo + hi;
}
// uint32 holding half2 -> packed f32x2
__device__ __forceinline__ ull h2_to_f2(unsigned u) {
    __half2 h = *reinterpret_cast<__half2*>(&u);
    float2 f = __half22float2(h);
    return pack2(f.x, f.y);
}

// ---------------------------------------------------------------------------
// Kernel 1: fold W2 (and b2,bh) into per-bucket heads + repack W1.
// ---------------------------------------------------------------------------
__global__ void lw_precompute(const float* __restrict__ W1,
                              const float* __restrict__ b1,
                              const float* __restrict__ W2,
                              const float* __restrict__ b2,
                              const float* __restrict__ Wh,
                              const float* __restrict__ bh) {
    int t = blockIdx.x * blockDim.x + threadIdx.x;
    if (t < NB * HID) {
        int id = t >> 5;
        int j  = t & 31;
        float acc = 0.f;
#pragma unroll
        for (int m = 0; m < HALF; m++)
            acc = fmaf(W2[j * HALF + m], Wh[id * HALF + m], acc);
        reinterpret_cast<__half*>(g_vh)[id * 36 + j] = __float2half_rn(acc);
    } else if (t < NB * HID + NB) {
        int id = t - NB * HID;
        float acc = bh[id];
#pragma unroll
        for (int m = 0; m < HALF; m++)
            acc = fmaf(b2[m], Wh[id * HALF + m], acc);
        g_c[id] = acc;
    } else if (t < NB * HID + NB + HID) {
        int j = t - (NB * HID + NB);
        int q = j >> 2, tt = j & 3;
        float* w = reinterpret_cast<float*>(g_W);
        w[(3 * q + 0) * 4 + tt] = W1[j];        // A
        w[(3 * q + 1) * 4 + tt] = W1[HID + j];  // B
        w[(3 * q + 2) * 4 + tt] = b1[j];        // C
    }
}

// ---------------------------------------------------------------------------
// Kernel 2: main. Two consecutive rows per thread; W1 from shared via
// broadcast LDS.128 (3 per q-step) so per-thread regs fit a 64-reg cap and
// 4 blocks/SM stay resident. fp16 v-table gather, packed f32x2 math.
// ---------------------------------------------------------------------------
__global__ __launch_bounds__(BLOCK, 4)
void lw_main(const float4* __restrict__ x2,
             const int2*   __restrict__ bk2,
             float2*       __restrict__ out2,
             int npairs,
             const float*  __restrict__ x_s,
             const int*    __restrict__ bk_s,
             float*        __restrict__ out_s,
             int B) {
    __shared__ uint2  s_vh[NB * 9];
    __shared__ float  s_c[NB];
    __shared__ float4 s_W[3 * HID / 4];

    for (int i = threadIdx.x; i < NB * 9; i += BLOCK) s_vh[i] = g_vh[i];
    if (threadIdx.x < NB) s_c[threadIdx.x] = g_c[threadIdx.x];
    if (threadIdx.x < 3 * HID / 4) s_W[threadIdx.x] = g_W[threadIdx.x];
    __syncthreads();

    const int T = gridDim.x * blockDim.x;
    const int tid = blockIdx.x * blockDim.x + threadIdx.x;

    if (tid < npairs) {
        int2   ids = bk2[tid];
        float4 xp  = x2[tid];
        for (int p = tid; p < npairs; ) {
            const int pn = p + T;
            int2   ids_n;
            float4 xp_n;
            if (pn < npairs) {           // prefetch next iteration's inputs
                ids_n = bk2[pn];
                xp_n  = x2[pn];
            }

            const unsigned i0 = min((unsigned)ids.x, NB - 1u);
            const unsigned i1 = min((unsigned)ids.y, NB - 1u);
            const uint2* v0 = s_vh + i0 * 9;
            const uint2* v1 = s_vh + i1 * 9;

            const ull xa0 = pack2(xp.x, xp.x), xb0 = pack2(xp.y, xp.y);
            const ull xa1 = pack2(xp.z, xp.z), xb1 = pack2(xp.w, xp.w);

            ull acc0 = pack2(s_c[i0], 0.f);   // c[id] folded into acc init
            ull acc1 = pack2(s_c[i1], 0.f);

#pragma unroll
            for (int q = 0; q < 8; q++) {
                const float4 wa = s_W[3 * q + 0];   // A[4q..4q+3] (broadcast)
                const float4 wb = s_W[3 * q + 1];   // B
                const float4 wc = s_W[3 * q + 2];   // C
                const ull a01 = pack2(wa.x, wa.y), a23 = pack2(wa.z, wa.w);
                const ull b01 = pack2(wb.x, wb.y), b23 = pack2(wb.z, wb.w);
                const ull c01 = pack2(wc.x, wc.y), c23 = pack2(wc.z, wc.w);
                const uint2 u0 = v0[q];
                const uint2 u1 = v1[q];
                ull t;
                t = fma2(xa0, a01, fma2(xb0, b01, c01));
                acc0 = fma2(relu2(t), h2_to_f2(u0.x), acc0);
                t = fma2(xa0, a23, fma2(xb0, b23, c23));
                acc0 = fma2(relu2(t), h2_to_f2(u0.y), acc0);
                t = fma2(xa1, a01, fma2(xb1, b01, c01));
                acc1 = fma2(relu2(t), h2_to_f2(u1.x), acc1);
                t = fma2(xa1, a23, fma2(xb1, b23, c23));
                acc1 = fma2(relu2(t), h2_to_f2(u1.y), acc1);
            }
            out2[p] = make_float2(hsum2(acc0), hsum2(acc1));

            p = pn;
            ids = ids_n;
            xp  = xp_n;
        }
    }

    // Odd-B tail: one scalar row handled by a single thread.
    if ((B & 1) && tid == 0) {
        const int r = B - 1;
        const unsigned id = min((unsigned)bk_s[r], NB - 1u);
        const uint2* v = s_vh + id * 9;
        const ull xa = pack2(x_s[2 * r], x_s[2 * r]);
        const ull xb = pack2(x_s[2 * r + 1], x_s[2 * r + 1]);
        ull acc = pack2(s_c[id], 0.f);
#pragma unroll
        for (int q = 0; q < 8; q++) {
            const float4 wa = s_W[3 * q + 0];
            const float4 wb = s_W[3 * q + 1];
            const float4 wc = s_W[3 * q + 2];
            const uint2 u = v[q];
            ull t;
            t = fma2(xa, pack2(wa.x, wa.y), fma2(xb, pack2(wb.x, wb.y), pack2(wc.x, wc.y)));
            acc = fma2(relu2(t), h2_to_f2(u.x), acc);
            t = fma2(xa, pack2(wa.z, wa.w), fma2(xb, pack2(wb.z, wb.w), pack2(wc.z, wc.w)));
            acc = fma2(relu2(t), h2_to_f2(u.y), acc);
        }
        out_s[r] = hsum2(acc);
    }
}

// ---------------------------------------------------------------------------
// Inputs (metadata order): x[B,2] f32, buckets[B] i32, W1[2,32], b1[32],
//                          W2[32,16], b2[16], Wh[50,16], bh[50]
// Output: float[B]
// ---------------------------------------------------------------------------
extern "C" void kernel_launch(void* const* d_in, const int* in_sizes, int n_in,
                              void* d_out, int out_size) {
    const float* x  = (const float*)d_in[0];
    const int*   bk = (const int*)d_in[1];
    const float* W1 = (const float*)d_in[2];
    const float* b1 = (const float*)d_in[3];
    const float* W2 = (const float*)d_in[4];
    const float* b2 = (const float*)d_in[5];
    const float* Wh = (const float*)d_in[6];
    const float* bh = (const float*)d_in[7];
    float* out = (float*)d_out;

    const int B = in_sizes[1];
    const int npairs = B >> 1;

    lw_precompute<<<14, 128>>>(W1, b1, W2, b2, Wh, bh);
    lw_main<<<GRID, BLOCK>>>((const float4*)x, (const int2*)bk, (float2*)out,
                             npairs, x, bk, out, B);
}

// round 16
// speedup vs baseline: 1.1454x; 1.1454x over previous
#include <cuda_runtime.h>
#include <cuda_fp16.h>
#include <cuda_bf16.h>

// Problem constants
#define NB     50      // buckets
#define HID    32
#define HALF   16
#define GRID   456     // 152 SMs * 3 resident blocks (persistent grid-stride)
#define BLOCK  256

typedef unsigned long long ull;

// Precomputed tables (device globals — no allocation allowed).
// g_vh: per bucket id, 9 uint2 slots (stride 9; slots 0..7 hold v[id][4q..4q+3]
// as 4 halves, slot 8 = pad). Bank-pair group of slot q is (9*id+q) mod 16 ->
// good spread for random ids, linear addressing (imm offsets).
__device__ uint2  g_vh[NB * 9];
__device__ float  g_c[NB];       // c[id] = b2 . Wh[id] + bh[id]  (fp32)
// W1/b1 interleaved for broadcast LDS.128:
//   g_W[3q+0] = {A[4q..4q+3]}  (A = W1[0][:])
//   g_W[3q+1] = {B[4q..4q+3]}  (B = W1[1][:])
//   g_W[3q+2] = {C[4q..4q+3]}  (C = b1[:])
__device__ float4 g_W[3 * HID / 4];

// ---------------------------------------------------------------------------
// Packed f32x2 helpers (Blackwell FFMA2 — only reachable via explicit PTX).
// ---------------------------------------------------------------------------
__device__ __forceinline__ ull pack2(float lo, float hi) {
    ull r;
    asm("mov.b64 %0, {%1, %2};" : "=l"(r) : "f"(lo), "f"(hi));
    return r;
}
__device__ __forceinline__ ull fma2(ull a, ull b, ull c) {
    ull d;
    asm("fma.rn.f32x2 %0, %1, %2, %3;" : "=l"(d) : "l"(a), "l"(b), "l"(c));
    return d;
}
__device__ __forceinline__ ull relu2(ull t) {
    float lo, hi;
    asm("mov.b64 {%0, %1}, %2;" : "=f"(lo), "=f"(hi) : "l"(t));
    return pack2(fmaxf(lo, 0.f), fmaxf(hi, 0.f));
}
__device__ __forceinline__ float hsum2(ull t) {
    float lo, hi;
    asm("mov.b64 {%0, %1}, %2;" : "=f"(lo), "=f"(hi) : "l"(t));
    return lo + hi;
}
// uint32 holding half2 -> packed f32x2
__device__ __forceinline__ ull h2_to_f2(unsigned u) {
    __half2 h = *reinterpret_cast<__half2*>(&u);
    float2 f = __half22float2(h);
    return pack2(f.x, f.y);
}

// ---------------------------------------------------------------------------
// Kernel 1: fold W2 (and b2,bh) into per-bucket heads + repack W1.
// ---------------------------------------------------------------------------
__global__ void lw_precompute(const float* __restrict__ W1,
                              const float* __restrict__ b1,
                              const float* __restrict__ W2,
                              const float* __restrict__ b2,
                              const float* __restrict__ Wh,
                              const float* __restrict__ bh) {
    int t = blockIdx.x * blockDim.x + threadIdx.x;
    if (t < NB * HID) {
        int id = t >> 5;
        int j  = t & 31;
        float acc = 0.f;
#pragma unroll
        for (int m = 0; m < HALF; m++)
            acc = fmaf(W2[j * HALF + m], Wh[id * HALF + m], acc);
        reinterpret_cast<__half*>(g_vh)[id * 36 + j] = __float2half_rn(acc);
    } else if (t < NB * HID + NB) {
        int id = t - NB * HID;
        float acc = bh[id];
#pragma unroll
        for (int m = 0; m < HALF; m++)
            acc = fmaf(b2[m], Wh[id * HALF + m], acc);
        g_c[id] = acc;
    } else if (t < NB * HID + NB + HID) {
        int j = t - (NB * HID + NB);
        int q = j >> 2, tt = j & 3;
        float* w = reinterpret_cast<float*>(g_W);
        w[(3 * q + 0) * 4 + tt] = W1[j];        // A
        w[(3 * q + 1) * 4 + tt] = W1[HID + j];  // B
        w[(3 * q + 2) * 4 + tt] = b1[j];        // C
    }
}

// ---------------------------------------------------------------------------
// Kernel 2: main. Two consecutive rows per thread; W1 from shared via
// broadcast LDS.128. 3 resident blocks/SM (85-reg budget — fits the audited
// live set, unlike the 64-reg cap which spilled). fp16 v-table gather,
// packed f32x2 math, next-iter prefetch of x/buckets.
// ---------------------------------------------------------------------------
__global__ __launch_bounds__(BLOCK, 3)
void lw_main(const float4* __restrict__ x2,
             const int2*   __restrict__ bk2,
             float2*       __restrict__ out2,
             int npairs,
             const float*  __restrict__ x_s,
             const int*    __restrict__ bk_s,
             float*        __restrict__ out_s,
             int B) {
    __shared__ uint2  s_vh[NB * 9];
    __shared__ float  s_c[NB];
    __shared__ float4 s_W[3 * HID / 4];

    for (int i = threadIdx.x; i < NB * 9; i += BLOCK) s_vh[i] = g_vh[i];
    if (threadIdx.x < NB) s_c[threadIdx.x] = g_c[threadIdx.x];
    if (threadIdx.x < 3 * HID / 4) s_W[threadIdx.x] = g_W[threadIdx.x];
    __syncthreads();

    const int T = gridDim.x * blockDim.x;
    const int tid = blockIdx.x * blockDim.x + threadIdx.x;

    if (tid < npairs) {
        int2   ids = bk2[tid];
        float4 xp  = x2[tid];
        for (int p = tid; p < npairs; ) {
            const int pn = p + T;
            int2   ids_n;
            float4 xp_n;
            if (pn < npairs) {           // prefetch next iteration's inputs
                ids_n = bk2[pn];
                xp_n  = x2[pn];
            }

            const unsigned i0 = min((unsigned)ids.x, NB - 1u);
            const unsigned i1 = min((unsigned)ids.y, NB - 1u);
            const uint2* v0 = s_vh + i0 * 9;
            const uint2* v1 = s_vh + i1 * 9;

            const ull xa0 = pack2(xp.x, xp.x), xb0 = pack2(xp.y, xp.y);
            const ull xa1 = pack2(xp.z, xp.z), xb1 = pack2(xp.w, xp.w);

            ull acc0 = pack2(s_c[i0], 0.f);   // c[id] folded into acc init
            ull acc1 = pack2(s_c[i1], 0.f);

#pragma unroll
            for (int q = 0; q < 8; q++) {
                const float4 wa = s_W[3 * q + 0];   // A[4q..4q+3] (broadcast)
                const float4 wb = s_W[3 * q + 1];   // B
                const float4 wc = s_W[3 * q + 2];   // C
                const uint2 u0 = v0[q];
                const uint2 u1 = v1[q];
                ull t;
                // first j-pair of this q-group: pairs built, used, retired
                {
                    const ull a01 = pack2(wa.x, wa.y);
                    const ull b01 = pack2(wb.x, wb.y);
                    const ull c01 = pack2(wc.x, wc.y);
                    t = fma2(xa0, a01, fma2(xb0, b01, c01));
                    acc0 = fma2(relu2(t), h2_to_f2(u0.x), acc0);
                    t = fma2(xa1, a01, fma2(xb1, b01, c01));
                    acc1 = fma2(relu2(t), h2_to_f2(u1.x), acc1);
                }
                // second j-pair
                {
                    const ull a23 = pack2(wa.z, wa.w);
                    const ull b23 = pack2(wb.z, wb.w);
                    const ull c23 = pack2(wc.z, wc.w);
                    t = fma2(xa0, a23, fma2(xb0, b23, c23));
                    acc0 = fma2(relu2(t), h2_to_f2(u0.y), acc0);
                    t = fma2(xa1, a23, fma2(xb1, b23, c23));
                    acc1 = fma2(relu2(t), h2_to_f2(u1.y), acc1);
                }
            }
            out2[p] = make_float2(hsum2(acc0), hsum2(acc1));

            p = pn;
            ids = ids_n;
            xp  = xp_n;
        }
    }

    // Odd-B tail: one scalar row handled by a single thread.
    if ((B & 1) && tid == 0) {
        const int r = B - 1;
        const unsigned id = min((unsigned)bk_s[r], NB - 1u);
        const uint2* v = s_vh + id * 9;
        const ull xa = pack2(x_s[2 * r], x_s[2 * r]);
        const ull xb = pack2(x_s[2 * r + 1], x_s[2 * r + 1]);
        ull acc = pack2(s_c[id], 0.f);
#pragma unroll
        for (int q = 0; q < 8; q++) {
            const float4 wa = s_W[3 * q + 0];
            const float4 wb = s_W[3 * q + 1];
            const float4 wc = s_W[3 * q + 2];
            const uint2 u = v[q];
            ull t;
            t = fma2(xa, pack2(wa.x, wa.y), fma2(xb, pack2(wb.x, wb.y), pack2(wc.x, wc.y)));
            acc = fma2(relu2(t), h2_to_f2(u.x), acc);
            t = fma2(xa, pack2(wa.z, wa.w), fma2(xb, pack2(wb.z, wb.w), pack2(wc.z, wc.w)));
            acc = fma2(relu2(t), h2_to_f2(u.y), acc);
        }
        out_s[r] = hsum2(acc);
    }
}

// ---------------------------------------------------------------------------
// Inputs (metadata order): x[B,2] f32, buckets[B] i32, W1[2,32], b1[32],
//                          W2[32,16], b2[16], Wh[50,16], bh[50]
// Output: float[B]
// ---------------------------------------------------------------------------
extern "C" void kernel_launch(void* const* d_in, const int* in_sizes, int n_in,
                              void* d_out, int out_size) {
    const float* x  = (const float*)d_in[0];
    const int*   bk = (const int*)d_in[1];
    const float* W1 = (const float*)d_in[2];
    const float* b1 = (const float*)d_in[3];
    const float* W2 = (const float*)d_in[4];
    const float* b2 = (const float*)d_in[5];
    const float* Wh = (const float*)d_in[6];
    const float* bh = (const float*)d_in[7];
    float* out = (float*)d_out;

    const int B = in_sizes[1];
    const int npairs = B >> 1;

    lw_precompute<<<14, 128>>>(W1, b1, W2, b2, Wh, bh);
    lw_main<<<GRID, BLOCK>>>((const float4*)x, (const int2*)bk, (float2*)out,
                             npairs, x, bk, out, B);
}

// round 17
// speedup vs baseline: 1.7736x; 1.5484x over previous
#include <cuda_runtime.h>
#include <cuda_fp16.h>
#include <cuda_bf16.h>

// Problem constants
#define NB     50      // buckets
#define HID    32
#define HALF   16
#define GRID   304     // 152 SMs * 2 resident blocks (persistent grid-stride)
#define BLOCK  256

typedef unsigned long long ull;

// Precomputed tables (device globals — no allocation allowed).
// g_vr: per bucket id one 80-byte record (20 floats, 16B aligned):
//   floats [0,16)  = 32 halves: v[id][0..31]  (v = W2 @ Wh[id], fp16)
//   float  [16]    = c[id] = b2 . Wh[id] + bh[id]  (fp32)
//   floats [17,20) = pad
// uint4 load k of a record covers v[8k..8k+7]; 16B-group = (5*id+k) mod 8
// (5 coprime 8 -> random ids spread over all bank groups).
__device__ __align__(16) float g_vr[NB * 20];
// W1/b1 interleaved for broadcast LDS.128:
//   g_W[3q+0]={A[4q..4q+3]}, g_W[3q+1]={B[..]}, g_W[3q+2]={C[..]}
//   (A = W1[0][:], B = W1[1][:], C = b1[:])
__device__ float4 g_W[3 * HID / 4];

// ---------------------------------------------------------------------------
// Packed f32x2 helpers (Blackwell FFMA2 — only reachable via explicit PTX).
// ---------------------------------------------------------------------------
__device__ __forceinline__ ull pack2(float lo, float hi) {
    ull r;
    asm("mov.b64 %0, {%1, %2};" : "=l"(r) : "f"(lo), "f"(hi));
    return r;
}
__device__ __forceinline__ ull fma2(ull a, ull b, ull c) {
    ull d;
    asm("fma.rn.f32x2 %0, %1, %2, %3;" : "=l"(d) : "l"(a), "l"(b), "l"(c));
    return d;
}
__device__ __forceinline__ ull relu2(ull t) {
    float lo, hi;
    asm("mov.b64 {%0, %1}, %2;" : "=f"(lo), "=f"(hi) : "l"(t));
    return pack2(fmaxf(lo, 0.f), fmaxf(hi, 0.f));
}
__device__ __forceinline__ float hsum2(ull t) {
    float lo, hi;
    asm("mov.b64 {%0, %1}, %2;" : "=f"(lo), "=f"(hi) : "l"(t));
    return lo + hi;
}
// uint32 holding half2 -> packed f32x2
__device__ __forceinline__ ull h2_to_f2(unsigned u) {
    __half2 h = *reinterpret_cast<__half2*>(&u);
    float2 f = __half22float2(h);
    return pack2(f.x, f.y);
}

// ---------------------------------------------------------------------------
// Kernel 1: fold W2 (and b2,bh) into per-bucket heads + repack W1.
// ---------------------------------------------------------------------------
__global__ void lw_precompute(const float* __restrict__ W1,
                              const float* __restrict__ b1,
                              const float* __restrict__ W2,
                              const float* __restrict__ b2,
                              const float* __restrict__ Wh,
                              const float* __restrict__ bh) {
    int t = blockIdx.x * blockDim.x + threadIdx.x;
    if (t < NB * HID) {
        int id = t >> 5;
        int j  = t & 31;
        float acc = 0.f;
#pragma unroll
        for (int m = 0; m < HALF; m++)
            acc = fmaf(W2[j * HALF + m], Wh[id * HALF + m], acc);
        reinterpret_cast<__half*>(g_vr)[id * 40 + j] = __float2half_rn(acc);
    } else if (t < NB * HID + NB) {
        int id = t - NB * HID;
        float acc = bh[id];
#pragma unroll
        for (int m = 0; m < HALF; m++)
            acc = fmaf(b2[m], Wh[id * HALF + m], acc);
        g_vr[id * 20 + 16] = acc;
    } else if (t < NB * HID + NB + HID) {
        int j = t - (NB * HID + NB);
        int q = j >> 2, tt = j & 3;
        float* w = reinterpret_cast<float*>(g_W);
        w[(3 * q + 0) * 4 + tt] = W1[j];        // A
        w[(3 * q + 1) * 4 + tt] = W1[HID + j];  // B
        w[(3 * q + 2) * 4 + tt] = b1[j];        // C
    }
}

// One uint4 of v (8 hidden units, j = 8k..8k+7) for one row.
__device__ __forceinline__ void row8(const ull xa, const ull xb, const uint4 u,
                                     const ull* ap, const ull* bp, const ull* cp,
                                     ull& acc) {
    ull t;
    t = fma2(xa, ap[0], fma2(xb, bp[0], cp[0])); acc = fma2(relu2(t), h2_to_f2(u.x), acc);
    t = fma2(xa, ap[1], fma2(xb, bp[1], cp[1])); acc = fma2(relu2(t), h2_to_f2(u.y), acc);
    t = fma2(xa, ap[2], fma2(xb, bp[2], cp[2])); acc = fma2(relu2(t), h2_to_f2(u.z), acc);
    t = fma2(xa, ap[3], fma2(xb, bp[3], cp[3])); acc = fma2(relu2(t), h2_to_f2(u.w), acc);
}

// ---------------------------------------------------------------------------
// Kernel 2: main. FOUR rows per thread (4 independent latency chains),
// W1 from shared via broadcast LDS.128, v-record gathered as uint4
// (4 LDS.128 per row), c folded into record. 2 blocks/SM, UNCAPPED 128-reg
// budget — no spills (unlike the 64/85-reg capped variants).
// ---------------------------------------------------------------------------
__global__ __launch_bounds__(BLOCK, 2)
void lw_main(const float4* __restrict__ x4,
             const int4*   __restrict__ bk4,
             float4*       __restrict__ out4,
             int nquads,
             const float*  __restrict__ x_s,
             const int*    __restrict__ bk_s,
             float*        __restrict__ out_s,
             int B) {
    __shared__ __align__(16) float s_vr[NB * 20];
    __shared__ float4 s_W[3 * HID / 4];

    {
        float4* dst = reinterpret_cast<float4*>(s_vr);
        const float4* src = reinterpret_cast<const float4*>(g_vr);
        for (int i = threadIdx.x; i < NB * 5; i += BLOCK) dst[i] = src[i];
        if (threadIdx.x < 3 * HID / 4) s_W[threadIdx.x] = g_W[threadIdx.x];
    }
    __syncthreads();

    const int T = gridDim.x * blockDim.x;
    const int tid = blockIdx.x * blockDim.x + threadIdx.x;

    if (tid < nquads) {
        int4   ids = bk4[tid];
        float4 xA  = x4[2 * tid + 0];
        float4 xB  = x4[2 * tid + 1];
        for (int p = tid; p < nquads; ) {
            const int pn = p + T;
            int4   ids_n;
            float4 xA_n, xB_n;
            if (pn < nquads) {           // prefetch next iteration's inputs
                ids_n = bk4[pn];
                xA_n  = x4[2 * pn + 0];
                xB_n  = x4[2 * pn + 1];
            }

            const unsigned i0 = min((unsigned)ids.x, NB - 1u);
            const unsigned i1 = min((unsigned)ids.y, NB - 1u);
            const unsigned i2 = min((unsigned)ids.z, NB - 1u);
            const unsigned i3 = min((unsigned)ids.w, NB - 1u);
            const uint4* v0 = reinterpret_cast<const uint4*>(s_vr + i0 * 20);
            const uint4* v1 = reinterpret_cast<const uint4*>(s_vr + i1 * 20);
            const uint4* v2 = reinterpret_cast<const uint4*>(s_vr + i2 * 20);
            const uint4* v3 = reinterpret_cast<const uint4*>(s_vr + i3 * 20);

            const ull xa0 = pack2(xA.x, xA.x), xb0 = pack2(xA.y, xA.y);
            const ull xa1 = pack2(xA.z, xA.z), xb1 = pack2(xA.w, xA.w);
            const ull xa2 = pack2(xB.x, xB.x), xb2 = pack2(xB.y, xB.y);
            const ull xa3 = pack2(xB.z, xB.z), xb3 = pack2(xB.w, xB.w);

            ull acc0 = pack2(s_vr[i0 * 20 + 16], 0.f);  // c[id] in acc init
            ull acc1 = pack2(s_vr[i1 * 20 + 16], 0.f);
            ull acc2 = pack2(s_vr[i2 * 20 + 16], 0.f);
            ull acc3 = pack2(s_vr[i3 * 20 + 16], 0.f);

#pragma unroll
            for (int k = 0; k < 4; k++) {               // j = 8k..8k+7
                const float4 wa0 = s_W[6 * k + 0];      // A[8k..8k+3]
                const float4 wb0 = s_W[6 * k + 1];
                const float4 wc0 = s_W[6 * k + 2];
                const float4 wa1 = s_W[6 * k + 3];      // A[8k+4..8k+7]
                const float4 wb1 = s_W[6 * k + 4];
                const float4 wc1 = s_W[6 * k + 5];
                const ull ap[4] = { pack2(wa0.x, wa0.y), pack2(wa0.z, wa0.w),
                                    pack2(wa1.x, wa1.y), pack2(wa1.z, wa1.w) };
                const ull bp[4] = { pack2(wb0.x, wb0.y), pack2(wb0.z, wb0.w),
                                    pack2(wb1.x, wb1.y), pack2(wb1.z, wb1.w) };
                const ull cp[4] = { pack2(wc0.x, wc0.y), pack2(wc0.z, wc0.w),
                                    pack2(wc1.x, wc1.y), pack2(wc1.z, wc1.w) };
                row8(xa0, xb0, v0[k], ap, bp, cp, acc0);
                row8(xa1, xb1, v1[k], ap, bp, cp, acc1);
                row8(xa2, xb2, v2[k], ap, bp, cp, acc2);
                row8(xa3, xb3, v3[k], ap, bp, cp, acc3);
            }
            out4[p] = make_float4(hsum2(acc0), hsum2(acc1),
                                  hsum2(acc2), hsum2(acc3));

            p = pn;
            ids = ids_n;
            xA  = xA_n;
            xB  = xB_n;
        }
    }

    // Tail: up to 3 scalar rows.
    const int rem = B & 3;
    if (tid < rem) {
        const int r = (nquads << 2) + tid;
        const unsigned id = min((unsigned)bk_s[r], NB - 1u);
        const unsigned* vv = reinterpret_cast<const unsigned*>(s_vr + id * 20);
        const ull xa = pack2(x_s[2 * r], x_s[2 * r]);
        const ull xb = pack2(x_s[2 * r + 1], x_s[2 * r + 1]);
        ull acc = pack2(s_vr[id * 20 + 16], 0.f);
#pragma unroll
        for (int jp = 0; jp < 16; jp++) {               // j-pair 2jp,2jp+1
            const int q = jp >> 1;
            const float4 wa = s_W[3 * q + 0];
            const float4 wb = s_W[3 * q + 1];
            const float4 wc = s_W[3 * q + 2];
            ull a, b, c;
            if (jp & 1) { a = pack2(wa.z, wa.w); b = pack2(wb.z, wb.w); c = pack2(wc.z, wc.w); }
            else        { a = pack2(wa.x, wa.y); b = pack2(wb.x, wb.y); c = pack2(wc.x, wc.y); }
            ull t = fma2(xa, a, fma2(xb, b, c));
            acc = fma2(relu2(t), h2_to_f2(vv[jp]), acc);
        }
        out_s[r] = hsum2(acc);
    }
}

// ---------------------------------------------------------------------------
// Inputs (metadata order): x[B,2] f32, buckets[B] i32, W1[2,32], b1[32],
//                          W2[32,16], b2[16], Wh[50,16], bh[50]
// Output: float[B]
// ---------------------------------------------------------------------------
extern "C" void kernel_launch(void* const* d_in, const int* in_sizes, int n_in,
                              void* d_out, int out_size) {
    const float* x  = (const float*)d_in[0];
    const int*   bk = (const int*)d_in[1];
    const float* W1 = (const float*)d_in[2];
    const float* b1 = (const float*)d_in[3];
    const float* W2 = (const float*)d_in[4];
    const float* b2 = (const float*)d_in[5];
    const float* Wh = (const float*)d_in[6];
    const float* bh = (const float*)d_in[7];
    float* out = (float*)d_out;

    const int B = in_sizes[1];
    const int nquads = B >> 2;

    lw_precompute<<<14, 128>>>(W1, b1, W2, b2, Wh, bh);
    lw_main<<<GRID, BLOCK>>>((const float4*)x, (const int4*)bk, (float4*)out,
                             nquads, x, bk, out, B);
}